// round 8
// baseline (speedup 1.0000x reference)
#include <cuda_runtime.h>

#define EMB   768
#define HEADS 8
#define HDIM  96
#define BATCH 4
#define SEQ   2048
#define ROWS  (BATCH*SEQ)      /* 8192 */
#define QKV_N (3*EMB)          /* 2304 */
#define INV_SCALE 0.10206207261596577f   /* 1/sqrt(96) */

typedef unsigned long long ull;

// ---------------- scratch (static device globals: allocation-free) ----------
// q, k stored d-major [bh][d][n]; v n-major [bh][n][d].
__device__ float g_q[BATCH*HEADS*HDIM*SEQ];
__device__ float g_k[BATCH*HEADS*HDIM*SEQ];
__device__ float g_v[BATCH*HEADS*SEQ*HDIM];
__device__ float g_attn[ROWS*EMB];

// ---------------- f32x2 helpers (Blackwell packed fp32, PTX-only) -----------
__device__ __forceinline__ ull pack2(float lo, float hi){
    ull r; asm("mov.b64 %0, {%1, %2};" : "=l"(r) : "f"(lo), "f"(hi)); return r;
}
__device__ __forceinline__ void unpack2(ull v, float& lo, float& hi){
    asm("mov.b64 {%0, %1}, %2;" : "=f"(lo), "=f"(hi) : "l"(v));
}
__device__ __forceinline__ ull fma2(ull a, ull b, ull c){
    ull d; asm("fma.rn.f32x2 %0, %1, %2, %3;" : "=l"(d) : "l"(a), "l"(b), "l"(c)); return d;
}
__device__ __forceinline__ ull mul2(ull a, ull b){
    ull d; asm("mul.rn.f32x2 %0, %1, %2;" : "=l"(d) : "l"(a), "l"(b)); return d;
}

// ============================================================================
// SGEMM: C[M x NC] = A[M x 768] * B[768 x NC] + bias, double-buffered SMEM.
//   MODE 0: A = x, scatter into g_q/g_k (d-major) and g_v (n-major)
//   MODE 1: A = g_attn, dense write to C (= d_out)
// Tile 128x128x16, 256 threads, 8x8 micro-tile via f32x2 pairs.
// One __syncthreads per k-tile; staging of tile t+1 overlaps FMAs on tile t.
// ============================================================================
#define AS_STRIDE 132
template<int NC, int MODE>
__global__ void __launch_bounds__(256) sgemm_kernel(const float* __restrict__ A,
                                                    const float* __restrict__ B,
                                                    const float* __restrict__ bias,
                                                    float* __restrict__ C)
{
    __shared__ __align__(16) float As[2][16*AS_STRIDE];
    __shared__ __align__(16) float Bs[2][16*128];

    const int tx = threadIdx.x, ty = threadIdx.y;
    const int tid = ty*16 + tx;
    const int bx = blockIdx.x, by = blockIdx.y;

    const float* Asrc = (MODE == 0) ? A : (const float*)g_attn;

    // staging assignment
    const int am = tid >> 2;            // 0..63 (rows am and am+64)
    const int ak = (tid & 3) << 2;      // 0,4,8,12
    const int bk = tid >> 5;            // 0..7  (k rows bk and bk+8)
    const int bn = (tid & 31) << 2;     // 0..124

    const float* Ap = Asrc + (size_t)(by*128 + am)*EMB + ak;
    const float* Bp = B + (size_t)bk*NC + bx*128 + bn;

    ull acc[8][4];
    #pragma unroll
    for (int i = 0; i < 8; ++i)
        #pragma unroll
        for (int j = 0; j < 4; ++j) acc[i][j] = 0ull;

    // load + stage tile 0
    {
        float4 a0 = *(const float4*)Ap;
        float4 a1 = *(const float4*)(Ap + 64*EMB);
        float4 b0 = *(const float4*)Bp;
        float4 b1 = *(const float4*)(Bp + 8*NC);
        As[0][(ak+0)*AS_STRIDE + am] = a0.x;  As[0][(ak+1)*AS_STRIDE + am] = a0.y;
        As[0][(ak+2)*AS_STRIDE + am] = a0.z;  As[0][(ak+3)*AS_STRIDE + am] = a0.w;
        As[0][(ak+0)*AS_STRIDE + am + 64] = a1.x;  As[0][(ak+1)*AS_STRIDE + am + 64] = a1.y;
        As[0][(ak+2)*AS_STRIDE + am + 64] = a1.z;  As[0][(ak+3)*AS_STRIDE + am + 64] = a1.w;
        *(float4*)&Bs[0][bk*128 + bn]     = b0;
        *(float4*)&Bs[0][(bk+8)*128 + bn] = b1;
    }
    __syncthreads();

    #pragma unroll 2
    for (int kt = 0; kt < EMB/16; ++kt){
        const int p = kt & 1;
        float4 na0, na1, nb0, nb1;
        const bool more = (kt + 1 < EMB/16);
        if (more){
            na0 = *(const float4*)(Ap + (kt+1)*16);
            na1 = *(const float4*)(Ap + 64*EMB + (kt+1)*16);
            nb0 = *(const float4*)(Bp + (size_t)((kt+1)*16)*NC);
            nb1 = *(const float4*)(Bp + (size_t)((kt+1)*16 + 8)*NC);
        }

        const float* Asp = As[p];
        const float* Bsp = Bs[p];
        #pragma unroll
        for (int k = 0; k < 16; ++k){
            float4 xa = *(const float4*)&Asp[k*AS_STRIDE + 4*ty];
            float4 xb = *(const float4*)&Asp[k*AS_STRIDE + 64 + 4*ty];
            ulonglong2 ya = *(const ulonglong2*)&Bsp[k*128 + 4*tx];
            ulonglong2 yb = *(const ulonglong2*)&Bsp[k*128 + 64 + 4*tx];
            float av8[8] = {xa.x, xa.y, xa.z, xa.w, xb.x, xb.y, xb.z, xb.w};
            #pragma unroll
            for (int i = 0; i < 8; ++i){
                ull ad = pack2(av8[i], av8[i]);
                acc[i][0] = fma2(ad, ya.x, acc[i][0]);
                acc[i][1] = fma2(ad, ya.y, acc[i][1]);
                acc[i][2] = fma2(ad, yb.x, acc[i][2]);
                acc[i][3] = fma2(ad, yb.y, acc[i][3]);
            }
        }

        if (more){
            float* Asn = As[p^1];
            float* Bsn = Bs[p^1];
            Asn[(ak+0)*AS_STRIDE + am] = na0.x;  Asn[(ak+1)*AS_STRIDE + am] = na0.y;
            Asn[(ak+2)*AS_STRIDE + am] = na0.z;  Asn[(ak+3)*AS_STRIDE + am] = na0.w;
            Asn[(ak+0)*AS_STRIDE + am + 64] = na1.x;  Asn[(ak+1)*AS_STRIDE + am + 64] = na1.y;
            Asn[(ak+2)*AS_STRIDE + am + 64] = na1.z;  Asn[(ak+3)*AS_STRIDE + am + 64] = na1.w;
            *(float4*)&Bsn[bk*128 + bn]     = nb0;
            *(float4*)&Bsn[(bk+8)*128 + bn] = nb1;
        }
        __syncthreads();
    }

    // ----- epilogue -----
    #pragma unroll
    for (int i = 0; i < 8; ++i){
        const int m = by*128 + ((i < 4) ? (4*ty + i) : (64 + 4*ty + i - 4));
        #pragma unroll
        for (int j = 0; j < 4; ++j){
            float lo, hi; unpack2(acc[i][j], lo, hi);
            const int c0 = bx*128 + ((j < 2) ? 4*tx : (64 + 4*tx)) + 2*(j & 1);
            const float v0 = lo + bias[c0];
            const float v1 = hi + bias[c0+1];
            if (MODE == 1){
                C[(size_t)m*NC + c0]     = v0;
                C[(size_t)m*NC + c0 + 1] = v1;
            } else {
                const int b = m >> 11;       // /2048
                const int n = m & 2047;
                #pragma unroll
                for (int e = 0; e < 2; ++e){
                    const int ccol = c0 + e;
                    const float val = e ? v1 : v0;
                    // qkv reshape (B,N,H,D,3): c = h*288 + d*3 + which
                    const int which = ccol % 3;
                    const int t     = ccol / 3;
                    const int d     = t % HDIM;
                    const int h     = t / HDIM;
                    const int bh    = b*HEADS + h;
                    if (which == 2)
                        g_v[((size_t)bh*SEQ + n)*HDIM + d] = val;          // [bh][n][d]
                    else {
                        float* dst = (which == 0) ? g_q : g_k;
                        dst[((size_t)bh*HDIM + d)*SEQ + n] = val;          // [bh][d][n]
                    }
                }
            }
        }
    }
}

// ============================================================================
// Flash attention, fp32 online softmax. One block = (bh, 128-query tile),
// 512 threads (16 warps/SM, 4/SMSP for latency hiding). Micro-tile 4x8.
// Thread (r = tid>>4 in 0..31, c = tid&15): rows 4r..4r+3,
//   S cols {4c..4c+3, 64+4c..64+4c+3}, O d-cols {4c..4c+3, 64+2c, 64+2c+1}.
// softmax(S) applied, 1/sqrt(D) AFTER (faithful to reference).
// ============================================================================
__global__ void __launch_bounds__(512, 1) flash_kernel()
{
    extern __shared__ __align__(16) float smf[];
    float* Qs = smf;                 // [96][128]  k-major
    float* Ks = Qs + 96*128;         // [96][128]  k-major
    float* Vs = Ks + 96*128;         // [128][96]  n-major
    float* Ps = Vs + 128*96;         // [128][132] row-major, padded

    const int tid = threadIdx.x;
    const int r = tid >> 4;          // 0..31
    const int c = tid & 15;          // 0..15
    const int n0 = blockIdx.x * 128;
    const int bh = blockIdx.y;

    const float* Qg = g_q + (size_t)bh*HDIM*SEQ;
    const float* Kg = g_k + (size_t)bh*HDIM*SEQ;
    const float* Vg = g_v + (size_t)bh*SEQ*HDIM;

    // load Q tile [96][128] — direct copy, conflict-free
    #pragma unroll
    for (int it = 0; it < 6; ++it){
        int f  = tid + it*512;         // 0..3071
        int d  = f >> 5;
        int n4 = (f & 31) << 2;
        *(float4*)&Qs[d*128 + n4] = *(const float4*)&Qg[(size_t)d*SEQ + n0 + n4];
    }

    ull o2[4][3];
    float mx[4], l[4];
    #pragma unroll
    for (int i = 0; i < 4; ++i){
        mx[i] = -1e30f; l[i] = 0.f;
        o2[i][0] = 0ull; o2[i][1] = 0ull; o2[i][2] = 0ull;
    }

    #pragma unroll 1
    for (int t = 0; t < SEQ/128; ++t){
        __syncthreads();   // prev iter done reading Ks/Vs (+ initial Qs order)

        const int kn0 = t*128;
        #pragma unroll
        for (int it = 0; it < 6; ++it){
            int f  = tid + it*512;
            int d  = f >> 5;
            int n4 = (f & 31) << 2;
            *(float4*)&Ks[d*128 + n4] = *(const float4*)&Kg[(size_t)d*SEQ + kn0 + n4];
            int rr = f / 24;
            int d4 = (f % 24) << 2;
            *(float4*)&Vs[rr*HDIM + d4] = *(const float4*)&Vg[(size_t)(kn0 + rr)*HDIM + d4];
        }
        __syncthreads();

        // ---- S = Q * K^T (128x128 tile), 4x8 per thread ----
        ull s2[4][4];
        #pragma unroll
        for (int i = 0; i < 4; ++i)
            #pragma unroll
            for (int j = 0; j < 4; ++j) s2[i][j] = 0ull;

        #pragma unroll 4
        for (int k = 0; k < HDIM; ++k){
            float4 q4 = *(const float4*)&Qs[k*128 + 4*r];
            ulonglong2 ka = *(const ulonglong2*)&Ks[k*128 + 4*c];
            ulonglong2 kb = *(const ulonglong2*)&Ks[k*128 + 64 + 4*c];
            float qv[4] = {q4.x, q4.y, q4.z, q4.w};
            #pragma unroll
            for (int i = 0; i < 4; ++i){
                ull qd = pack2(qv[i], qv[i]);
                s2[i][0] = fma2(qd, ka.x, s2[i][0]);
                s2[i][1] = fma2(qd, ka.y, s2[i][1]);
                s2[i][2] = fma2(qd, kb.x, s2[i][2]);
                s2[i][3] = fma2(qd, kb.y, s2[i][3]);
            }
        }

        // ---- online softmax (rows owned by 16-lane group, width-16 shfl) ----
        #pragma unroll
        for (int i = 0; i < 4; ++i){
            float s[8];
            unpack2(s2[i][0], s[0], s[1]);
            unpack2(s2[i][1], s[2], s[3]);
            unpack2(s2[i][2], s[4], s[5]);
            unpack2(s2[i][3], s[6], s[7]);
            float tm = fmaxf(fmaxf(fmaxf(s[0], s[1]), fmaxf(s[2], s[3])),
                             fmaxf(fmaxf(s[4], s[5]), fmaxf(s[6], s[7])));
            #pragma unroll
            for (int off = 8; off > 0; off >>= 1)
                tm = fmaxf(tm, __shfl_xor_sync(0xffffffffu, tm, off, 16));
            const float mnew  = fmaxf(mx[i], tm);
            const float alpha = __expf(mx[i] - mnew);
            float p[8], rs = 0.f;
            #pragma unroll
            for (int u = 0; u < 8; ++u){ p[u] = __expf(s[u] - mnew); rs += p[u]; }
            #pragma unroll
            for (int off = 8; off > 0; off >>= 1)
                rs += __shfl_xor_sync(0xffffffffu, rs, off, 16);
            l[i] = l[i]*alpha + rs;
            mx[i] = mnew;
            const ull a2 = pack2(alpha, alpha);
            o2[i][0] = mul2(a2, o2[i][0]);
            o2[i][1] = mul2(a2, o2[i][1]);
            o2[i][2] = mul2(a2, o2[i][2]);
            *(float4*)&Ps[(4*r + i)*132 + 4*c]      = make_float4(p[0], p[1], p[2], p[3]);
            *(float4*)&Ps[(4*r + i)*132 + 64 + 4*c] = make_float4(p[4], p[5], p[6], p[7]);
        }
        __syncthreads();

        // ---- O += P * V ; rows 4r+i, d in {4c..4c+3, 64+2c, 64+2c+1} ----
        #pragma unroll 1
        for (int kk0 = 0; kk0 < 128; kk0 += 4){
            float4 pr[4];
            #pragma unroll
            for (int i = 0; i < 4; ++i)
                pr[i] = *(const float4*)&Ps[(4*r + i)*132 + kk0];
            #pragma unroll
            for (int u = 0; u < 4; ++u){
                const int kk = kk0 + u;
                ulonglong2 va = *(const ulonglong2*)&Vs[kk*HDIM + 4*c];
                ull        vb = *(const ull*)&Vs[kk*HDIM + 64 + 2*c];
                #pragma unroll
                for (int i = 0; i < 4; ++i){
                    const float pv = ((const float*)&pr[i])[u];
                    const ull pd = pack2(pv, pv);
                    o2[i][0] = fma2(pd, va.x, o2[i][0]);
                    o2[i][1] = fma2(pd, va.y, o2[i][1]);
                    o2[i][2] = fma2(pd, vb,   o2[i][2]);
                }
            }
        }
    }

    // ---- normalize, apply post-softmax inv_scale, write b n (h d) layout ----
    const int b = bh / HEADS, h = bh % HEADS;
    #pragma unroll
    for (int i = 0; i < 4; ++i){
        const float sc = INV_SCALE / l[i];
        float* dst = g_attn + (size_t)(b*SEQ + n0 + 4*r + i)*EMB + h*HDIM;
        float p0, p1, p2, p3, p4, p5;
        unpack2(o2[i][0], p0, p1);
        unpack2(o2[i][1], p2, p3);
        unpack2(o2[i][2], p4, p5);
        *(float4*)&dst[4*c] = make_float4(p0*sc, p1*sc, p2*sc, p3*sc);
        dst[64 + 2*c]     = p4*sc;
        dst[64 + 2*c + 1] = p5*sc;
    }
}

// ============================================================================
extern "C" void kernel_launch(void* const* d_in, const int* in_sizes, int n_in,
                              void* d_out, int out_size)
{
    const float* x      = (const float*)d_in[0];
    const float* w_qkv  = (const float*)d_in[1];
    const float* b_qkv  = (const float*)d_in[2];
    const float* w_proj = (const float*)d_in[3];
    const float* b_proj = (const float*)d_in[4];
    float* out = (float*)d_out;

    const int smem = (96*128 + 96*128 + 128*96 + 128*132) * (int)sizeof(float); // 215040
    cudaFuncSetAttribute(flash_kernel, cudaFuncAttributeMaxDynamicSharedMemorySize, smem);

    dim3 blk(16, 16);
    // 1) QKV GEMM + bias + scatter (q,k d-major; v n-major)
    sgemm_kernel<QKV_N, 0><<<dim3(QKV_N/128, ROWS/128), blk>>>(x, w_qkv, b_qkv, nullptr);
    // 2) flash attention: (128-query tile, b*h), 512 threads/block
    flash_kernel<<<dim3(SEQ/128, BATCH*HEADS), 512, smem>>>();
    // 3) output projection + bias
    sgemm_kernel<EMB, 1><<<dim3(EMB/128, ROWS/128), blk>>>(nullptr, w_proj, b_proj, out);
}